// round 5
// baseline (speedup 1.0000x reference)
#include <cuda_runtime.h>
#include <math.h>
#include <cstdint>

#define MAX_S 4096
__device__ float4 g_coeffs[2 * MAX_S];

#define BLOCK 256
#define TILE 4096                  // samples staged per block (16 KB)
#define TILE4 (TILE / 4)           // float4 groups per tile (1024)

__global__ void spline_coeff_kernel(const float2* __restrict__ ctrl,
                                    const float2* __restrict__ joint,
                                    int S) {
    int s = blockIdx.x * blockDim.x + threadIdx.x;
    if (s >= S) return;
    float2 p0 = joint[s];
    float2 p3 = joint[s + 1];
    float2 p1 = ctrl[2 * s];
    float2 p2 = ctrl[2 * s + 1];

    float c1x = 3.0f * (p1.x - p0.x);
    float c1y = 3.0f * (p1.y - p0.y);
    float c2x = 3.0f * p0.x - 6.0f * p1.x + 3.0f * p2.x;
    float c2y = 3.0f * p0.y - 6.0f * p1.y + 3.0f * p2.y;
    float c3x = -p0.x + 3.0f * p1.x - 3.0f * p2.x + p3.x;
    float c3y = -p0.y + 3.0f * p1.y - 3.0f * p2.y + p3.y;

    g_coeffs[2 * s + 0] = make_float4(p0.x, p0.y, c1x, c1y);
    g_coeffs[2 * s + 1] = make_float4(c2x, c2y, c3x, c3y);
}

__global__ void __launch_bounds__(BLOCK)
spline_eval_bulk(const float* __restrict__ t,
                 float4* __restrict__ out4,
                 int n4, float Sf, int S) {
    __shared__ alignas(128) float4 s_t[TILE4];
    __shared__ alignas(8) uint64_t s_mbar;

    const int tid = threadIdx.x;
    const int g0 = blockIdx.x * TILE4;                 // first float4 group of tile
    const int gcnt = min(TILE4, n4 - g0);              // groups in this tile (>0 by grid)
    const uint32_t bytes = (uint32_t)gcnt * 16u;

    uint32_t mbar = (uint32_t)__cvta_generic_to_shared(&s_mbar);
    uint32_t dst  = (uint32_t)__cvta_generic_to_shared(&s_t[0]);

    if (tid == 0) {
        asm volatile("mbarrier.init.shared.b64 [%0], 1;" :: "r"(mbar) : "memory");
    }
    __syncthreads();   // init visible to all before anyone waits

    if (tid == 0) {
        asm volatile("mbarrier.arrive.expect_tx.shared.b64 _, [%0], %1;"
                     :: "r"(mbar), "r"(bytes) : "memory");
        asm volatile("cp.async.bulk.shared::cta.global.mbarrier::complete_tx::bytes "
                     "[%0], [%1], %2, [%3];"
                     :: "r"(dst), "l"(t + (size_t)g0 * 4), "r"(bytes), "r"(mbar)
                     : "memory");
    }

    // wait phase 0 (acquire orders subsequent smem reads)
    {
        uint32_t done = 0;
        while (!done) {
            asm volatile(
                "{\n\t.reg .pred p;\n\t"
                "mbarrier.try_wait.parity.acquire.cta.shared::cta.b64 p, [%1], %2;\n\t"
                "selp.b32 %0, 1, 0, p;\n\t}"
                : "=r"(done) : "r"(mbar), "r"(0u) : "memory");
        }
    }

#pragma unroll
    for (int k = 0; k < 4; k++) {
        int rel = tid + k * BLOCK;                 // group within tile
        if (rel >= gcnt) break;
        int gi = g0 + rel;                         // global float4 group

        float4 tv = s_t[rel];
        float ts[4] = {tv.x, tv.y, tv.z, tv.w};
        float rx[4], ry[4];
#pragma unroll
        for (int j = 0; j < 4; j++) {
            float tc = fminf(ts[j], 1.0f);
            float u = Sf * tc;
            int sg = (int)floorf(u);
            float l = u - (float)sg;
            if (sg >= S) { sg = S - 1; l = 1.0f; }

            float4 a = __ldg(&g_coeffs[2 * sg + 0]);   // c0.x c0.y c1.x c1.y
            float4 b = __ldg(&g_coeffs[2 * sg + 1]);   // c2.x c2.y c3.x c3.y

            float l2 = l * l;
            float l3 = l2 * l;
            rx[j] = fmaf(b.z, l3, fmaf(b.x, l2, fmaf(a.z, l, a.x)));
            ry[j] = fmaf(b.w, l3, fmaf(b.y, l2, fmaf(a.w, l, a.y)));
        }
        __stcs(out4 + 2 * gi + 0, make_float4(rx[0], ry[0], rx[1], ry[1]));
        __stcs(out4 + 2 * gi + 1, make_float4(rx[2], ry[2], rx[3], ry[3]));
    }
}

// Scalar tail for n % 4 != 0 (not hit for N = 8388608)
__global__ void spline_eval_tail(const float* __restrict__ t,
                                 float2* __restrict__ out,
                                 int start, int n, float Sf, int S) {
    int i = start + blockIdx.x * blockDim.x + threadIdx.x;
    if (i >= n) return;
    float tc = fminf(t[i], 1.0f);
    float u = Sf * tc;
    int sg = (int)floorf(u);
    float l = u - (float)sg;
    if (sg >= S) { sg = S - 1; l = 1.0f; }
    float4 a = __ldg(&g_coeffs[2 * sg + 0]);
    float4 b = __ldg(&g_coeffs[2 * sg + 1]);
    float l2 = l * l;
    float l3 = l2 * l;
    float x = fmaf(b.z, l3, fmaf(b.x, l2, fmaf(a.z, l, a.x)));
    float y = fmaf(b.w, l3, fmaf(b.y, l2, fmaf(a.w, l, a.y)));
    out[i] = make_float2(x, y);
}

extern "C" void kernel_launch(void* const* d_in, const int* in_sizes, int n_in,
                              void* d_out, int out_size) {
    const float* t = (const float*)d_in[0];
    const float2* ctrl = (const float2*)d_in[1];
    const float2* joint = (const float2*)d_in[2];

    int n = in_sizes[0];
    int S = in_sizes[2] / 2 - 1;

    {
        int threads = 256;
        int blocks = (S + threads - 1) / threads;
        spline_coeff_kernel<<<blocks, threads>>>(ctrl, joint, S);
    }

    int n4 = n / 4;
    if (n4 > 0) {
        int blocks = (n4 + TILE4 - 1) / TILE4;
        spline_eval_bulk<<<blocks, BLOCK>>>(t, (float4*)d_out, n4, (float)S, S);
    }
    int rem = n - n4 * 4;
    if (rem > 0) {
        spline_eval_tail<<<1, 128>>>(t, (float2*)d_out, n4 * 4, n, (float)S, S);
    }
}

// round 6
// speedup vs baseline: 1.1652x; 1.1652x over previous
#include <cuda_runtime.h>
#include <math.h>

#define MAX_S 4096
__device__ float4 g_coeffs[2 * MAX_S];

#define BLOCK 256

__global__ void spline_coeff_kernel(const float2* __restrict__ ctrl,
                                    const float2* __restrict__ joint,
                                    int S) {
    int s = blockIdx.x * blockDim.x + threadIdx.x;
    if (s >= S) return;
    float2 p0 = joint[s];
    float2 p3 = joint[s + 1];
    float2 p1 = ctrl[2 * s];
    float2 p2 = ctrl[2 * s + 1];

    float c1x = 3.0f * (p1.x - p0.x);
    float c1y = 3.0f * (p1.y - p0.y);
    float c2x = 3.0f * p0.x - 6.0f * p1.x + 3.0f * p2.x;
    float c2y = 3.0f * p0.y - 6.0f * p1.y + 3.0f * p2.y;
    float c3x = -p0.x + 3.0f * p1.x - 3.0f * p2.x + p3.x;
    float c3y = -p0.y + 3.0f * p1.y - 3.0f * p2.y + p3.y;

    g_coeffs[2 * s + 0] = make_float4(p0.x, p0.y, c1x, c1y);
    g_coeffs[2 * s + 1] = make_float4(c2x, c2y, c3x, c3y);
}

__device__ __forceinline__ void eval_one(const float4& a, const float4& b,
                                         float l, float& x, float& y) {
    float l2 = l * l;
    float l3 = l2 * l;
    x = fmaf(b.z, l3, fmaf(b.x, l2, fmaf(a.z, l, a.x)));
    y = fmaf(b.w, l3, fmaf(b.y, l2, fmaf(a.w, l, a.y)));
}

__global__ void __launch_bounds__(BLOCK)
spline_eval_kernel(const float4* __restrict__ t4,
                   float4* __restrict__ out4,
                   int n4, float Sf, int S) {
    int i = blockIdx.x * BLOCK + threadIdx.x;
    bool valid = (i < n4);
    // clamp OOB threads to the last group so warp-uniformity logic stays sane
    int ii = valid ? i : (n4 - 1);

    float4 tv = t4[ii];
    float ts[4] = {tv.x, tv.y, tv.z, tv.w};

    int   seg[4];
    float lt[4];
#pragma unroll
    for (int j = 0; j < 4; j++) {
        float tc = fminf(ts[j], 1.0f);
        float u = Sf * tc;
        int sg = (int)u;                 // u >= 0: trunc == floor
        float l = u - (float)sg;
        if (sg >= S) { sg = S - 1; l = 1.0f; }
        seg[j] = sg;
        lt[j] = l;
    }

    // Warp-uniform segment? (t sorted: warp min = lane0 sample0, max = lane31 sample3)
    int lo = __shfl_sync(0xFFFFFFFFu, seg[0], 0);
    int hi = __shfl_sync(0xFFFFFFFFu, seg[3], 31);

    float rx[4], ry[4];
    if (lo == hi) {
        // one segment for the whole warp: 2 broadcast loads, reused 4x
        float4 a = __ldg(&g_coeffs[2 * lo + 0]);
        float4 b = __ldg(&g_coeffs[2 * lo + 1]);
#pragma unroll
        for (int j = 0; j < 4; j++)
            eval_one(a, b, lt[j], rx[j], ry[j]);
    } else {
        // boundary warp (~6% of warps): per-sample gather
#pragma unroll
        for (int j = 0; j < 4; j++) {
            float4 a = __ldg(&g_coeffs[2 * seg[j] + 0]);
            float4 b = __ldg(&g_coeffs[2 * seg[j] + 1]);
            eval_one(a, b, lt[j], rx[j], ry[j]);
        }
    }

    if (valid) {
        __stcs(out4 + 2 * i + 0, make_float4(rx[0], ry[0], rx[1], ry[1]));
        __stcs(out4 + 2 * i + 1, make_float4(rx[2], ry[2], rx[3], ry[3]));
    }
}

// Scalar tail for n % 4 != 0 (not hit for N = 8388608)
__global__ void spline_eval_tail(const float* __restrict__ t,
                                 float2* __restrict__ out,
                                 int start, int n, float Sf, int S) {
    int i = start + blockIdx.x * blockDim.x + threadIdx.x;
    if (i >= n) return;
    float tc = fminf(t[i], 1.0f);
    float u = Sf * tc;
    int sg = (int)u;
    float l = u - (float)sg;
    if (sg >= S) { sg = S - 1; l = 1.0f; }
    float4 a = __ldg(&g_coeffs[2 * sg + 0]);
    float4 b = __ldg(&g_coeffs[2 * sg + 1]);
    float x, y;
    eval_one(a, b, l, x, y);
    out[i] = make_float2(x, y);
}

extern "C" void kernel_launch(void* const* d_in, const int* in_sizes, int n_in,
                              void* d_out, int out_size) {
    const float* t = (const float*)d_in[0];
    const float2* ctrl = (const float2*)d_in[1];
    const float2* joint = (const float2*)d_in[2];

    int n = in_sizes[0];
    int S = in_sizes[2] / 2 - 1;

    {
        int threads = 256;
        int blocks = (S + threads - 1) / threads;
        spline_coeff_kernel<<<blocks, threads>>>(ctrl, joint, S);
    }

    int n4 = n / 4;
    if (n4 > 0) {
        int blocks = (n4 + BLOCK - 1) / BLOCK;
        spline_eval_kernel<<<blocks, BLOCK>>>((const float4*)t, (float4*)d_out,
                                              n4, (float)S, S);
    }
    int rem = n - n4 * 4;
    if (rem > 0) {
        spline_eval_tail<<<1, 128>>>(t, (float2*)d_out, n4 * 4, n, (float)S, S);
    }
}